// round 2
// baseline (speedup 1.0000x reference)
#include <cuda_runtime.h>
#include <math.h>

// Problem constants
#define D_   128
#define K_   32
#define HW_  4096   // H*W = 64*64
#define B_   16
#define TILE_ 128   // positions per CTA
#define NT_   128   // threads per CTA
#define XPAD_ 132   // padded row length for X tile (floats): 4-way max bank conflicts, 16B aligned
#define APAD_ 36    // padded row length for A tile

#define SMEM_FLOATS (K_*D_ + K_ + K_ + TILE_*XPAD_ + TILE_*APAD_)
#define SMEM_BYTES  (SMEM_FLOATS * 4)

__global__ void zero_kernel(float* out, int nelem) {
    int i = blockIdx.x * blockDim.x + threadIdx.x;
    if (i < nelem) out[i] = 0.0f;
}

__global__ __launch_bounds__(NT_, 2)
void enc_kernel(const float* __restrict__ x,
                const float* __restrict__ cw,
                const float* __restrict__ scale,
                float* __restrict__ out) {
    extern __shared__ float smem[];
    float* Cs  = smem;                 // [K_][D_]
    float* c2s = Cs + K_ * D_;         // [K_]
    float* ss  = c2s + K_;             // [K_]
    float* Xs  = ss + K_;              // [TILE_][XPAD_]
    float* As  = Xs + TILE_ * XPAD_;   // [TILE_][APAD_]

    const int t    = threadIdx.x;
    const int b    = blockIdx.x >> 5;   // HW_/TILE_ = 32 tiles per batch
    const int tile = blockIdx.x & 31;
    const int n0   = tile * TILE_;

    // Stage codewords + scale
    for (int i = t; i < K_ * D_; i += NT_) Cs[i] = cw[i];
    if (t < K_) ss[t] = scale[t];
    __syncthreads();
    if (t < K_) {
        float s = 0.f;
        const float* c = Cs + t * D_;
        #pragma unroll 8
        for (int d = 0; d < D_; d++) s += c[d] * c[d];
        c2s[t] = s;
    }
    __syncthreads();

    // ---------------- Phase 1: xc[k] = X[n]·C[k], stage X tile ----------------
    const float* xb = x + (size_t)b * D_ * HW_ + n0 + t;  // stride HW_ over d, coalesced over t
    float xc[K_];
    #pragma unroll
    for (int k = 0; k < K_; k++) xc[k] = 0.f;
    float x2 = 0.f;

    #pragma unroll 4
    for (int d0 = 0; d0 < D_; d0 += 4) {
        float v0 = xb[(size_t)(d0 + 0) * HW_];
        float v1 = xb[(size_t)(d0 + 1) * HW_];
        float v2 = xb[(size_t)(d0 + 2) * HW_];
        float v3 = xb[(size_t)(d0 + 3) * HW_];
        x2 += v0 * v0; x2 += v1 * v1; x2 += v2 * v2; x2 += v3 * v3;
        *(float4*)&Xs[t * XPAD_ + d0] = make_float4(v0, v1, v2, v3);
        #pragma unroll
        for (int k = 0; k < K_; k++) {
            float4 c = *(const float4*)&Cs[k * D_ + d0];  // broadcast across warp
            xc[k] += v0 * c.x;
            xc[k] += v1 * c.y;
            xc[k] += v2 * c.z;
            xc[k] += v3 * c.w;
        }
    }

    // ---------------- Softmax over K (registers) ----------------
    float a[K_];
    float mx = -1e30f;
    #pragma unroll
    for (int k = 0; k < K_; k++) {
        a[k] = ss[k] * (x2 - 2.f * xc[k] + c2s[k]);
        mx = fmaxf(mx, a[k]);
    }
    float sum = 0.f;
    #pragma unroll
    for (int k = 0; k < K_; k++) {
        float e = __expf(a[k] - mx);
        a[k] = e;
        sum += e;
    }
    float inv = 1.f / sum;
    #pragma unroll
    for (int k = 0; k < K_; k += 4) {
        *(float4*)&As[t * APAD_ + k] =
            make_float4(a[k] * inv, a[k + 1] * inv, a[k + 2] * inv, a[k + 3] * inv);
    }
    __syncthreads();

    // ---------------- Phase 2: E_part[k][d] = sum_n A[n][k]*X[n][d] ----------------
    const int lane  = t & 31;
    const int kg    = t >> 5;       // 0..3 -> 8 k's each
    const int kbase = kg * 8;
    const int dbase = lane * 4;     // 4 d's each

    float acc[8][4];
    float sa[8];
    #pragma unroll
    for (int i = 0; i < 8; i++) {
        sa[i] = 0.f;
        #pragma unroll
        for (int j = 0; j < 4; j++) acc[i][j] = 0.f;
    }

    #pragma unroll 2
    for (int n = 0; n < TILE_; n++) {
        float4 xv = *(const float4*)&Xs[n * XPAD_ + dbase];   // conflict-free
        float4 a0 = *(const float4*)&As[n * APAD_ + kbase];   // broadcast
        float4 a1 = *(const float4*)&As[n * APAD_ + kbase + 4];
        float av[8] = {a0.x, a0.y, a0.z, a0.w, a1.x, a1.y, a1.z, a1.w};
        #pragma unroll
        for (int i = 0; i < 8; i++) {
            sa[i]     += av[i];
            acc[i][0] += av[i] * xv.x;
            acc[i][1] += av[i] * xv.y;
            acc[i][2] += av[i] * xv.z;
            acc[i][3] += av[i] * xv.w;
        }
    }

    // Fold -sumA*C into the per-CTA partial, accumulate to global
    float* ob = out + b * K_ * D_;
    #pragma unroll
    for (int i = 0; i < 8; i++) {
        int k = kbase + i;
        #pragma unroll
        for (int j = 0; j < 4; j++) {
            int d = dbase + j;
            atomicAdd(&ob[k * D_ + d], acc[i][j] - sa[i] * Cs[k * D_ + d]);
        }
    }
}

extern "C" void kernel_launch(void* const* d_in, const int* in_sizes, int n_in,
                              void* d_out, int out_size) {
    const float* x  = (const float*)d_in[0];   // (B, D, H, W) fp32
    const float* cw = (const float*)d_in[1];   // (K, D) fp32
    const float* sc = (const float*)d_in[2];   // (K,) fp32
    float* out = (float*)d_out;                // (B, K, D) fp32

    cudaFuncSetAttribute(enc_kernel, cudaFuncAttributeMaxDynamicSharedMemorySize, SMEM_BYTES);

    const int nelem = B_ * K_ * D_;
    zero_kernel<<<(nelem + 255) / 256, 256>>>(out, nelem);
    enc_kernel<<<B_ * (HW_ / TILE_), NT_, SMEM_BYTES>>>(x, cw, sc, out);
}

// round 3
// speedup vs baseline: 1.0380x; 1.0380x over previous
#include <cuda_runtime.h>
#include <math.h>

// Problem constants
#define D_    128
#define K_    32
#define HW_   4096   // H*W = 64*64
#define B_    16
#define TILE_ 128    // positions per CTA
#define NT_   256    // threads per CTA (two threads cooperate per position)
#define XPAD_ 132    // padded row length for X tile (floats): conflict-free, 16B aligned
#define APAD_ 36     // padded row length for A / partial buffer

#define SMEM_FLOATS (K_*D_ + K_ + K_ + TILE_*XPAD_ + TILE_*APAD_)
#define SMEM_BYTES  (SMEM_FLOATS * 4)

__global__ void zero_kernel(float* out, int nelem) {
    int i = blockIdx.x * blockDim.x + threadIdx.x;
    if (i < nelem) out[i] = 0.0f;
}

__global__ __launch_bounds__(NT_, 2)
void enc_kernel(const float* __restrict__ x,
                const float* __restrict__ cw,
                const float* __restrict__ scale,
                float* __restrict__ out) {
    extern __shared__ float smem[];
    float* Cs  = smem;                 // [K_][D_]
    float* c2s = Cs + K_ * D_;         // [K_]
    float* ss  = c2s + K_;             // [K_]
    float* Xs  = ss + K_;              // [TILE_][XPAD_]
    float* As  = Xs + TILE_ * XPAD_;   // [TILE_][APAD_]  (partials, then softmax A)

    const int t    = threadIdx.x;
    const int b    = blockIdx.x >> 5;   // 32 tiles per batch
    const int tile = blockIdx.x & 31;
    const int n0   = tile * TILE_;

    // Stage codewords + scale
    for (int i = t; i < K_ * D_; i += NT_) Cs[i] = cw[i];
    if (t < K_) ss[t] = scale[t];
    __syncthreads();
    if (t < K_) {
        float s = 0.f;
        const float* c = Cs + t * D_;
        #pragma unroll 8
        for (int d = 0; d < D_; d++) s += c[d] * c[d];
        c2s[t] = s;
    }
    __syncthreads();

    // ---------------- Phase 1: xc[k] = X[n]·C[k] over half the d-range ----------------
    const int half = t >> 7;          // 0: d in [0,64), 1: d in [64,128)
    const int n    = t & 127;         // position within tile
    const int dof  = half * 64;

    const float* xb = x + (size_t)b * D_ * HW_ + (size_t)dof * HW_ + n0 + n;
    float xc[K_];
    #pragma unroll
    for (int k = 0; k < K_; k++) xc[k] = 0.f;
    float x2 = 0.f;

    #pragma unroll 2
    for (int d0 = 0; d0 < 64; d0 += 4) {
        float v0 = xb[(size_t)(d0 + 0) * HW_];
        float v1 = xb[(size_t)(d0 + 1) * HW_];
        float v2 = xb[(size_t)(d0 + 2) * HW_];
        float v3 = xb[(size_t)(d0 + 3) * HW_];
        x2 += v0 * v0; x2 += v1 * v1; x2 += v2 * v2; x2 += v3 * v3;
        *(float4*)&Xs[n * XPAD_ + dof + d0] = make_float4(v0, v1, v2, v3);
        #pragma unroll
        for (int k = 0; k < K_; k++) {
            float4 c = *(const float4*)&Cs[k * D_ + dof + d0];  // broadcast
            xc[k] += v0 * c.x;
            xc[k] += v1 * c.y;
            xc[k] += v2 * c.z;
            xc[k] += v3 * c.w;
        }
    }

    // ---------------- Combine halves + softmax (lower half finishes) ----------------
    if (half == 1) {
        #pragma unroll
        for (int k = 0; k < K_; k += 4)
            *(float4*)&As[n * APAD_ + k] = make_float4(xc[k], xc[k+1], xc[k+2], xc[k+3]);
        As[n * APAD_ + K_] = x2;
    }
    __syncthreads();
    if (half == 0) {
        #pragma unroll
        for (int k = 0; k < K_; k += 4) {
            float4 p = *(const float4*)&As[n * APAD_ + k];
            xc[k]   += p.x; xc[k+1] += p.y; xc[k+2] += p.z; xc[k+3] += p.w;
        }
        x2 += As[n * APAD_ + K_];

        float a[K_];
        float mx = -1e30f;
        #pragma unroll
        for (int k = 0; k < K_; k++) {
            a[k] = ss[k] * (x2 - 2.f * xc[k] + c2s[k]);
            mx = fmaxf(mx, a[k]);
        }
        float sum = 0.f;
        #pragma unroll
        for (int k = 0; k < K_; k++) {
            float e = __expf(a[k] - mx);
            a[k] = e;
            sum += e;
        }
        float inv = 1.f / sum;
        #pragma unroll
        for (int k = 0; k < K_; k += 4) {
            *(float4*)&As[n * APAD_ + k] =
                make_float4(a[k] * inv, a[k+1] * inv, a[k+2] * inv, a[k+3] * inv);
        }
    }
    __syncthreads();

    // ---------------- Phase 2: E_part[k][d] = sum_n A[n][k]*X[n][d] ----------------
    // 256 threads: 8 k-groups (4 k each) x 32 d-groups (4 d each)
    const int lane  = t & 31;
    const int kg    = t >> 5;       // 0..7
    const int kbase = kg * 4;
    const int dbase = lane * 4;

    float acc[4][4];
    float sa[4];
    #pragma unroll
    for (int i = 0; i < 4; i++) {
        sa[i] = 0.f;
        #pragma unroll
        for (int j = 0; j < 4; j++) acc[i][j] = 0.f;
    }

    #pragma unroll 2
    for (int nn = 0; nn < TILE_; nn++) {
        float4 xv = *(const float4*)&Xs[nn * XPAD_ + dbase];   // conflict-free
        float4 a0 = *(const float4*)&As[nn * APAD_ + kbase];   // broadcast
        float av[4] = {a0.x, a0.y, a0.z, a0.w};
        #pragma unroll
        for (int i = 0; i < 4; i++) {
            sa[i]     += av[i];
            acc[i][0] += av[i] * xv.x;
            acc[i][1] += av[i] * xv.y;
            acc[i][2] += av[i] * xv.z;
            acc[i][3] += av[i] * xv.w;
        }
    }

    // Fold -sumA*C into the per-CTA partial, accumulate to global
    float* ob = out + b * K_ * D_;
    #pragma unroll
    for (int i = 0; i < 4; i++) {
        int k = kbase + i;
        #pragma unroll
        for (int j = 0; j < 4; j++) {
            int d = dbase + j;
            atomicAdd(&ob[k * D_ + d], acc[i][j] - sa[i] * Cs[k * D_ + d]);
        }
    }
}

extern "C" void kernel_launch(void* const* d_in, const int* in_sizes, int n_in,
                              void* d_out, int out_size) {
    const float* x  = (const float*)d_in[0];   // (B, D, H, W) fp32
    const float* cw = (const float*)d_in[1];   // (K, D) fp32
    const float* sc = (const float*)d_in[2];   // (K,) fp32
    float* out = (float*)d_out;                // (B, K, D) fp32

    cudaFuncSetAttribute(enc_kernel, cudaFuncAttributeMaxDynamicSharedMemorySize, SMEM_BYTES);

    const int nelem = B_ * K_ * D_;
    zero_kernel<<<(nelem + 255) / 256, 256>>>(out, nelem);
    enc_kernel<<<B_ * (HW_ / TILE_), NT_, SMEM_BYTES>>>(x, cw, sc, out);
}

// round 7
// speedup vs baseline: 1.3912x; 1.3403x over previous
#include <cuda_runtime.h>
#include <math.h>
#include <stdint.h>

#define D_    128
#define K_    32
#define HW_   4096
#define B_    16
#define TILE_ 128
#define NT_   256

#define XPAD_ 136   // Xs row stride (words): frag loads conflict-free (8*tg+g distinct)
#define CPAD_ 136
#define APAD_ 40

#define SMEM_WORDS (D_*XPAD_ + K_*CPAD_ + TILE_*APAD_ + K_ + K_ + 2*TILE_ + 4*K_)
#define SMEM_BYTES (SMEM_WORDS * 4)

__global__ void zero_kernel(float* out, int nelem) {
    int i = blockIdx.x * blockDim.x + threadIdx.x;
    if (i < nelem) out[i] = 0.0f;
}

__device__ __forceinline__ uint32_t f2tf(float f) {
    uint32_t u;
    asm("cvt.rna.tf32.f32 %0, %1;" : "=r"(u) : "f"(f));
    return u;
}

__device__ __forceinline__ void mma_tf32(float c[4],
                                         uint32_t a0, uint32_t a1, uint32_t a2, uint32_t a3,
                                         uint32_t b0, uint32_t b1) {
    asm volatile(
        "mma.sync.aligned.m16n8k8.row.col.f32.tf32.tf32.f32 "
        "{%0,%1,%2,%3}, {%4,%5,%6,%7}, {%8,%9}, {%0,%1,%2,%3};\n"
        : "+f"(c[0]), "+f"(c[1]), "+f"(c[2]), "+f"(c[3])
        : "r"(a0), "r"(a1), "r"(a2), "r"(a3), "r"(b0), "r"(b1));
}

__global__ __launch_bounds__(NT_, 2)
void enc_kernel(const float* __restrict__ x,
                const float* __restrict__ cw,
                const float* __restrict__ scale,
                float* __restrict__ out) {
    extern __shared__ float smem[];
    float* Xs  = smem;                   // [D_][XPAD_]  X tile, [d][n] layout
    float* Cs  = Xs + D_ * XPAD_;        // [K_][CPAD_]  codewords [k][d]
    float* As  = Cs + K_ * CPAD_;        // [TILE_][APAD_] softmax A [n][k]
    float* c2s = As + TILE_ * APAD_;     // [K_]
    float* ss  = c2s + K_;               // [K_]
    float* x2p = ss + K_;                // [2][TILE_]  x2 half-sums
    float* sa4 = x2p + 2 * TILE_;        // [4][K_]     per-warp-group sumA partials

    const int t    = threadIdx.x;
    const int b    = blockIdx.x >> 5;     // 32 tiles per batch
    const int tile = blockIdx.x & 31;
    const int n0   = tile * TILE_;
    const int warp = t >> 5;
    const int lane = t & 31;
    const int g    = lane >> 2;           // groupID (0..7)
    const int tg   = lane & 3;            // thread-in-group

    // ---- stage C (coalesced; one warp per k-row per iter) ----
    for (int idx = t * 4; idx < K_ * D_; idx += NT_ * 4) {
        int k = idx >> 7, d = idx & 127;
        *(float4*)&Cs[k * CPAD_ + d] = *(const float4*)&cw[idx];
    }
    if (t < K_) ss[t] = scale[t];
    // c2 from gmem (L2-hot), independent of smem staging
    if (t < K_) {
        float s = 0.f;
        const float* c = cw + t * D_;
        #pragma unroll 8
        for (int d = 0; d < D_; d++) s += c[d] * c[d];
        c2s[t] = s;
    }

    // ---- stage X tile: [d][n] natural layout, fully coalesced (512B per warp-iter) ----
    const float* xb = x + (size_t)b * D_ * HW_ + n0;
    for (int idx = t * 4; idx < D_ * TILE_; idx += NT_ * 4) {
        int d = idx >> 7, c = idx & 127;
        *(float4*)&Xs[d * XPAD_ + c] = *(const float4*)&xb[(size_t)d * HW_ + c];
    }
    __syncthreads();

    // ---- x2[n] exact fp32 (column sums, conflict-free: lanes = consecutive n) ----
    {
        int n = t & 127, h = t >> 7;
        float s = 0.f;
        #pragma unroll 8
        for (int d = h * 64; d < h * 64 + 64; d++) {
            float v = Xs[d * XPAD_ + n];
            s += v * v;
        }
        x2p[h * TILE_ + n] = s;
    }
    __syncthreads();

    // ---- Phase 1: D1[n,k] = sum_d X[n,d]*C[k,d] via tf32 mma ----
    // warp w owns n in [16w, 16w+16); 4 k-tiles of 8; 16 d-steps of 8
    const int n0w = warp * 16;
    float c1[4][4];
    #pragma unroll
    for (int i = 0; i < 4; i++)
        #pragma unroll
        for (int j = 0; j < 4; j++) c1[i][j] = 0.f;

    #pragma unroll 4
    for (int dstep = 0; dstep < 16; dstep++) {
        int d0 = dstep * 8;
        uint32_t a0 = f2tf(Xs[(d0 + tg) * XPAD_ + n0w + g]);
        uint32_t a1 = f2tf(Xs[(d0 + tg) * XPAD_ + n0w + g + 8]);
        uint32_t a2 = f2tf(Xs[(d0 + tg + 4) * XPAD_ + n0w + g]);
        uint32_t a3 = f2tf(Xs[(d0 + tg + 4) * XPAD_ + n0w + g + 8]);
        #pragma unroll
        for (int kt = 0; kt < 4; kt++) {
            int k0 = kt * 8;
            uint32_t b0 = f2tf(Cs[(k0 + g) * CPAD_ + d0 + tg]);
            uint32_t b1 = f2tf(Cs[(k0 + g) * CPAD_ + d0 + tg + 4]);
            mma_tf32(c1[kt], a0, a1, a2, a3, b0, b1);
        }
    }

    // ---- softmax on fragments (rows r0 = n0w+g, r1 = n0w+g+8; k = kt*8 + 2tg + {0,1}) ----
    {
        int r0 = n0w + g, r1 = r0 + 8;
        float x2r0 = x2p[r0] + x2p[TILE_ + r0];
        float x2r1 = x2p[r1] + x2p[TILE_ + r1];
        float l0[8], l1[8];
        #pragma unroll
        for (int kt = 0; kt < 4; kt++) {
            int k = kt * 8 + 2 * tg;
            float s0 = ss[k], s1 = ss[k + 1];
            float q0 = c2s[k], q1 = c2s[k + 1];
            l0[2*kt]   = s0 * (x2r0 - 2.f * c1[kt][0] + q0);
            l0[2*kt+1] = s1 * (x2r0 - 2.f * c1[kt][1] + q1);
            l1[2*kt]   = s0 * (x2r1 - 2.f * c1[kt][2] + q0);
            l1[2*kt+1] = s1 * (x2r1 - 2.f * c1[kt][3] + q1);
        }
        float m0 = -1e30f, m1 = -1e30f;
        #pragma unroll
        for (int i = 0; i < 8; i++) { m0 = fmaxf(m0, l0[i]); m1 = fmaxf(m1, l1[i]); }
        // rows live in 4-lane groups (same g): bfly over tg
        m0 = fmaxf(m0, __shfl_xor_sync(0xffffffffu, m0, 1));
        m0 = fmaxf(m0, __shfl_xor_sync(0xffffffffu, m0, 2));
        m1 = fmaxf(m1, __shfl_xor_sync(0xffffffffu, m1, 1));
        m1 = fmaxf(m1, __shfl_xor_sync(0xffffffffu, m1, 2));
        float s0 = 0.f, s1 = 0.f;
        #pragma unroll
        for (int i = 0; i < 8; i++) {
            l0[i] = __expf(l0[i] - m0); s0 += l0[i];
            l1[i] = __expf(l1[i] - m1); s1 += l1[i];
        }
        s0 += __shfl_xor_sync(0xffffffffu, s0, 1);
        s0 += __shfl_xor_sync(0xffffffffu, s0, 2);
        s1 += __shfl_xor_sync(0xffffffffu, s1, 1);
        s1 += __shfl_xor_sync(0xffffffffu, s1, 2);
        float i0 = 1.f / s0, i1 = 1.f / s1;
        #pragma unroll
        for (int kt = 0; kt < 4; kt++) {
            int k = kt * 8 + 2 * tg;
            *(float2*)&As[r0 * APAD_ + k] = make_float2(l0[2*kt] * i0, l0[2*kt+1] * i0);
            *(float2*)&As[r1 * APAD_ + k] = make_float2(l1[2*kt] * i1, l1[2*kt+1] * i1);
        }
    }
    __syncthreads();

    // ---- sa partials: warp w<4 sums A over n in [32w,32w+32), lane = k (conflict-free) ----
    if (warp < 4) {
        float s = 0.f;
        #pragma unroll 8
        for (int n = warp * 32; n < warp * 32 + 32; n++) s += As[n * APAD_ + lane];
        sa4[warp * K_ + lane] = s;
    }

    // ---- Phase 2: E^T[d,k] = sum_n X[n,d]*A[n,k] via tf32 mma ----
    const int d0w = warp * 16;
    float c2f[4][4];
    #pragma unroll
    for (int i = 0; i < 4; i++)
        #pragma unroll
        for (int j = 0; j < 4; j++) c2f[i][j] = 0.f;

    #pragma unroll 4
    for (int nstep = 0; nstep < 16; nstep++) {
        int nk0 = nstep * 8;
        uint32_t a0 = f2tf(Xs[(d0w + g) * XPAD_ + nk0 + tg]);
        uint32_t a1 = f2tf(Xs[(d0w + g + 8) * XPAD_ + nk0 + tg]);
        uint32_t a2 = f2tf(Xs[(d0w + g) * XPAD_ + nk0 + tg + 4]);
        uint32_t a3 = f2tf(Xs[(d0w + g + 8) * XPAD_ + nk0 + tg + 4]);
        #pragma unroll
        for (int kt = 0; kt < 4; kt++) {
            int k0 = kt * 8;
            uint32_t b0 = f2tf(As[(nk0 + tg) * APAD_ + k0 + g]);
            uint32_t b1 = f2tf(As[(nk0 + tg + 4) * APAD_ + k0 + g]);
            mma_tf32(c2f[kt], a0, a1, a2, a3, b0, b1);
        }
    }
    __syncthreads();  // sa4 complete before epilogue reads it

    // ---- epilogue: out[b][k][d] += E^T[d][k] - sa[k]*C[k][d] ----
    float* ob = out + b * K_ * D_;
    #pragma unroll
    for (int kt = 0; kt < 4; kt++) {
        int k = kt * 8 + 2 * tg;
        float saA = sa4[k]        + sa4[K_ + k]     + sa4[2*K_ + k]     + sa4[3*K_ + k];
        float saB = sa4[k + 1]    + sa4[K_ + k + 1] + sa4[2*K_ + k + 1] + sa4[3*K_ + k + 1];
        int dA = d0w + g, dB = d0w + g + 8;
        atomicAdd(&ob[k       * D_ + dA], c2f[kt][0] - saA * Cs[k       * CPAD_ + dA]);
        atomicAdd(&ob[(k + 1) * D_ + dA], c2f[kt][1] - saB * Cs[(k + 1) * CPAD_ + dA]);
        atomicAdd(&ob[k       * D_ + dB], c2f[kt][2] - saA * Cs[k       * CPAD_ + dB]);
        atomicAdd(&ob[(k + 1) * D_ + dB], c2f[kt][3] - saB * Cs[(k + 1) * CPAD_ + dB]);
    }
}

extern "C" void kernel_launch(void* const* d_in, const int* in_sizes, int n_in,
                              void* d_out, int out_size) {
    const float* x  = (const float*)d_in[0];   // (B, D, H, W) fp32
    const float* cw = (const float*)d_in[1];   // (K, D) fp32
    const float* sc = (const float*)d_in[2];   // (K,) fp32
    float* out = (float*)d_out;                // (B, K, D) fp32

    cudaFuncSetAttribute(enc_kernel, cudaFuncAttributeMaxDynamicSharedMemorySize, SMEM_BYTES);

    const int nelem = B_ * K_ * D_;
    zero_kernel<<<(nelem + 255) / 256, 256>>>(out, nelem);
    enc_kernel<<<B_ * (HW_ / TILE_), NT_, SMEM_BYTES>>>(x, cw, sc, out);
}